// round 1
// baseline (speedup 1.0000x reference)
#include <cuda_runtime.h>

// ConformerAttention: B=8, S=1024, D=512, H=8, hd=64, P=2047
// rel_shift identity: shifted[i,j] = raw[i, j + (S-1) - i], i.e. uses p row r = 1023 + j - i.

#define CB 8
#define CS 1024
#define CD 512
#define CH 8
#define CHD 64
#define CP 2047
#define MTOK (CB*CS)   // 8192

// -------- scratch (allocation-free: device globals) --------
__device__ float g_h [MTOK*CD];            // LayerNorm output [8192, 512]
__device__ float g_q [CB*CH*CS*CHD];       // [B,H,S,hd]
__device__ float g_k [CB*CH*CS*CHD];
__device__ float g_v [CB*CH*CS*CHD];
__device__ float g_p [CH*CP*CHD];          // [H,P,hd]
__device__ float g_ao[MTOK*CD];            // attention output in [B,S,D]

// ============================ LayerNorm ============================
__global__ void __launch_bounds__(128) ln_kernel(const float* __restrict__ x,
    const float* __restrict__ w, const float* __restrict__ b, float* __restrict__ out)
{
    int row = blockIdx.x;
    int t = threadIdx.x;
    const float* xr = x + (size_t)row * CD;
    float4 v = *(const float4*)(xr + t * 4);
    float s = v.x + v.y + v.z + v.w;
    #pragma unroll
    for (int o = 16; o; o >>= 1) s += __shfl_xor_sync(0xffffffffu, s, o);
    __shared__ float ws1[4], ws2[4];
    if ((t & 31) == 0) ws1[t >> 5] = s;
    __syncthreads();
    float mean = (ws1[0] + ws1[1] + ws1[2] + ws1[3]) * (1.0f / 512.0f);
    float dx = v.x - mean, dy = v.y - mean, dz = v.z - mean, dw = v.w - mean;
    float q = dx*dx + dy*dy + dz*dz + dw*dw;
    #pragma unroll
    for (int o = 16; o; o >>= 1) q += __shfl_xor_sync(0xffffffffu, q, o);
    if ((t & 31) == 0) ws2[t >> 5] = q;
    __syncthreads();
    float var = (ws2[0] + ws2[1] + ws2[2] + ws2[3]) * (1.0f / 512.0f);
    float rstd = rsqrtf(var + 1e-5f);
    float4 wv = *(const float4*)(w + t * 4);
    float4 bv = *(const float4*)(b + t * 4);
    float4 o4;
    o4.x = dx * rstd * wv.x + bv.x;
    o4.y = dy * rstd * wv.y + bv.y;
    o4.z = dz * rstd * wv.z + bv.z;
    o4.w = dw * rstd * wv.w + bv.w;
    *(float4*)(out + (size_t)row * CD + t * 4) = o4;
}

// ============================ GEMM: C = A @ W^T ============================
// A: [M, 512] row-major, W: [512, 512] row-major (torch Linear weight)
// mode 0: out = q/k/v scratch in [B,H,S,hd] layout, +bias
// mode 3: out = g_p in [H,P,hd] layout, no bias, M=2047 (guarded)
// mode 4: out = plain [M,512], + bias + resid (residual x)
__global__ void __launch_bounds__(256) gemm_kernel(
    const float* __restrict__ A, int M,
    const float* __restrict__ W,
    const float* __restrict__ bias,
    const float* __restrict__ resid,
    float* __restrict__ out, int mode)
{
    __shared__ float As[16][68];
    __shared__ float Ws[16][68];
    int tid = threadIdx.x;
    int m0 = blockIdx.y * 64, n0 = blockIdx.x * 64;
    int lm = tid >> 2;            // 0..63
    int lk = (tid & 3) * 4;       // 0,4,8,12
    int tx = tid & 15, ty = tid >> 4;
    float acc[4][4] = {};
    for (int k0 = 0; k0 < 512; k0 += 16) {
        float4 a4 = make_float4(0.f, 0.f, 0.f, 0.f);
        int am = m0 + lm;
        if (am < M) a4 = *(const float4*)(A + (size_t)am * 512 + k0 + lk);
        As[lk+0][lm] = a4.x; As[lk+1][lm] = a4.y; As[lk+2][lm] = a4.z; As[lk+3][lm] = a4.w;
        float4 w4 = *(const float4*)(W + (size_t)(n0 + lm) * 512 + k0 + lk);
        Ws[lk+0][lm] = w4.x; Ws[lk+1][lm] = w4.y; Ws[lk+2][lm] = w4.z; Ws[lk+3][lm] = w4.w;
        __syncthreads();
        #pragma unroll
        for (int kk = 0; kk < 16; kk++) {
            float4 av = *(const float4*)&As[kk][ty * 4];
            float4 wv = *(const float4*)&Ws[kk][tx * 4];
            acc[0][0] += av.x * wv.x; acc[0][1] += av.x * wv.y;
            acc[0][2] += av.x * wv.z; acc[0][3] += av.x * wv.w;
            acc[1][0] += av.y * wv.x; acc[1][1] += av.y * wv.y;
            acc[1][2] += av.y * wv.z; acc[1][3] += av.y * wv.w;
            acc[2][0] += av.z * wv.x; acc[2][1] += av.z * wv.y;
            acc[2][2] += av.z * wv.z; acc[2][3] += av.z * wv.w;
            acc[3][0] += av.w * wv.x; acc[3][1] += av.w * wv.y;
            acc[3][2] += av.w * wv.z; acc[3][3] += av.w * wv.w;
        }
        __syncthreads();
    }
    #pragma unroll
    for (int i = 0; i < 4; i++) {
        int m = m0 + ty * 4 + i;
        #pragma unroll
        for (int j = 0; j < 4; j++) {
            int n = n0 + tx * 4 + j;
            float val = acc[i][j];
            if (mode == 0) {
                val += bias[n];
                int bi = m >> 10, sr = m & 1023, hh = n >> 6, dd = n & 63;
                out[((size_t)(bi * CH + hh) << 16) + ((size_t)sr << 6) + dd] = val;
            } else if (mode == 3) {
                if (m < M) {
                    int hh = n >> 6, dd = n & 63;
                    out[((size_t)hh * CP + m) * 64 + dd] = val;
                }
            } else { // mode 4
                size_t idx = (size_t)m * 512 + n;
                out[idx] = val + bias[n] + resid[idx];
            }
        }
    }
}

// ============================ Fused attention ============================
// One block per (b, h, 32-query tile). Scores [32][1024] live in shared.
// score[i,j] = (q_i+bu)·k_j + (q_i+bv)·p_{1023+j-i}, scaled by 1/8, softmax, then @V.
constexpr int SC_F  = 32 * 1024;   // score tile
constexpr int Q_F   = 32 * 68;     // q+bias tiles (stride 68 rows)
constexpr int K_F   = 64 * 68;     // k/v chunk
constexpr int P_F   = 95 * 68;     // p band chunk (rr in [0,94])
constexpr int SMEM_FLOATS = SC_F + 2 * Q_F + K_F + P_F;
constexpr int SMEM_BYTES  = SMEM_FLOATS * 4;   // 191,728 B

__global__ void __launch_bounds__(256) attn_kernel(const float* __restrict__ bu,
    const float* __restrict__ bvp, float* __restrict__ ao)
{
    extern __shared__ float sm[];
    float* sc  = sm;                 // [32][1024]
    float* qus = sm + SC_F;          // [32][68]  (q + bias_u)
    float* qvs = qus + Q_F;          // [32][68]  (q + bias_v)
    float* kst = qvs + Q_F;          // [64][68]  (k chunk; reused for v)
    float* pst = kst + K_F;          // [95][68]  (p band chunk)

    int tid = threadIdx.x;
    int blk = blockIdx.x;
    int qt = blk & 31;               // 32 q-tiles per (b,h)
    int bh = blk >> 5;               // 0..63
    int h  = bh & 7;
    int i0 = qt * 32;
    const float* qbase = g_q + (size_t)bh * (CS * CHD);
    const float* kbase = g_k + (size_t)bh * (CS * CHD);
    const float* vbase = g_v + (size_t)bh * (CS * CHD);
    const float* pbase = g_p + (size_t)h  * (CP * CHD);

    // Phase A: load q tile with both bias variants
    {
        int d = tid & 63, il0 = tid >> 6;
        float u  = bu [h * 64 + d];
        float vb = bvp[h * 64 + d];
        #pragma unroll
        for (int rep = 0; rep < 8; rep++) {
            int i = il0 + rep * 4;
            float qv = qbase[(size_t)(i0 + i) * 64 + d];
            qus[i * 68 + d] = qv + u;
            qvs[i * 68 + d] = qv + vb;
        }
    }

    int w = tid >> 5, l = tid & 31;
    int ib = w * 4;                  // this warp's 4 query rows

    // Phase B: scores, 16 key-chunks of 64
    for (int jc = 0; jc < 16; jc++) {
        __syncthreads();
        int j0 = jc * 64;
        {
            int d = tid & 63, jl0 = tid >> 6;
            #pragma unroll
            for (int rep = 0; rep < 16; rep++) {
                int jl = jl0 + rep * 4;
                kst[jl * 68 + d] = kbase[(size_t)(j0 + jl) * 64 + d];
            }
            int rbase = 1023 + j0 - i0 - 31;   // r = rbase + rr, rr = jl - il + 31
            for (int idx = tid; idx < 95 * 64; idx += 256) {
                int rr = idx >> 6, d2 = idx & 63;
                pst[rr * 68 + d2] = pbase[(size_t)(rbase + rr) * 64 + d2];
            }
        }
        __syncthreads();
        float acc[4][2] = {};
        for (int d = 0; d < 64; d += 4) {
            float4 k0 = *(const float4*)&kst[l * 68 + d];
            float4 k1 = *(const float4*)&kst[(l + 32) * 68 + d];
            #pragma unroll
            for (int q = 0; q < 4; q++) {
                int il = ib + q;
                float4 au = *(const float4*)&qus[il * 68 + d];
                float4 av = *(const float4*)&qvs[il * 68 + d];
                float4 p0 = *(const float4*)&pst[(31 + l - il) * 68 + d];
                float4 p1 = *(const float4*)&pst[(63 + l - il) * 68 + d];
                acc[q][0] += au.x * k0.x + au.y * k0.y + au.z * k0.z + au.w * k0.w
                           + av.x * p0.x + av.y * p0.y + av.z * p0.z + av.w * p0.w;
                acc[q][1] += au.x * k1.x + au.y * k1.y + au.z * k1.z + au.w * k1.w
                           + av.x * p1.x + av.y * p1.y + av.z * p1.z + av.w * p1.w;
            }
        }
        #pragma unroll
        for (int q = 0; q < 4; q++) {
            sc[(ib + q) * 1024 + j0 + l]      = acc[q][0] * 0.125f;
            sc[(ib + q) * 1024 + j0 + l + 32] = acc[q][1] * 0.125f;
        }
    }
    __syncthreads();

    // Phase C: softmax, 4 rows per warp
    for (int r = w; r < 32; r += 8) {
        float* row = sc + r * 1024;
        float mx = -1e30f;
        for (int j = l; j < 1024; j += 32) mx = fmaxf(mx, row[j]);
        #pragma unroll
        for (int o = 16; o; o >>= 1) mx = fmaxf(mx, __shfl_xor_sync(0xffffffffu, mx, o));
        float sum = 0.f;
        for (int j = l; j < 1024; j += 32) {
            float e = __expf(row[j] - mx);
            row[j] = e;
            sum += e;
        }
        #pragma unroll
        for (int o = 16; o; o >>= 1) sum += __shfl_xor_sync(0xffffffffu, sum, o);
        float inv = 1.0f / sum;
        for (int j = l; j < 1024; j += 32) row[j] *= inv;
    }

    // Phase D: O = attn @ V
    float oa[4][2] = {};
    for (int jc = 0; jc < 16; jc++) {
        __syncthreads();
        int j0 = jc * 64;
        {
            int d = tid & 63, jl0 = tid >> 6;
            #pragma unroll
            for (int rep = 0; rep < 16; rep++) {
                int jl = jl0 + rep * 4;
                kst[jl * 68 + d] = vbase[(size_t)(j0 + jl) * 64 + d];
            }
        }
        __syncthreads();
        for (int jj = 0; jj < 64; jj++) {
            float v0 = kst[jj * 68 + l], v1 = kst[jj * 68 + l + 32];
            #pragma unroll
            for (int q = 0; q < 4; q++) {
                float a = sc[(ib + q) * 1024 + j0 + jj];
                oa[q][0] += a * v0;
                oa[q][1] += a * v1;
            }
        }
    }
    int b = bh >> 3;
    #pragma unroll
    for (int q = 0; q < 4; q++) {
        size_t row = (size_t)(b * 1024 + i0 + ib + q) * 512 + h * 64;
        ao[row + l]      = oa[q][0];
        ao[row + l + 32] = oa[q][1];
    }
}

// ============================ launch ============================
extern "C" void kernel_launch(void* const* d_in, const int* in_sizes, int n_in,
                              void* d_out, int out_size)
{
    const float* x       = (const float*)d_in[0];
    const float* pos_emb = (const float*)d_in[1];
    const float* ln_w    = (const float*)d_in[2];
    const float* ln_b    = (const float*)d_in[3];
    const float* Wq      = (const float*)d_in[4];
    const float* bq      = (const float*)d_in[5];
    const float* Wk      = (const float*)d_in[6];
    const float* bk      = (const float*)d_in[7];
    const float* Wv      = (const float*)d_in[8];
    const float* bv      = (const float*)d_in[9];
    const float* Wo      = (const float*)d_in[10];
    const float* bo      = (const float*)d_in[11];
    const float* Wp      = (const float*)d_in[12];
    const float* pbu     = (const float*)d_in[13];
    const float* pbv     = (const float*)d_in[14];
    float* out = (float*)d_out;

    float *hp, *qp, *kp, *vp, *pp, *aop;
    cudaGetSymbolAddress((void**)&hp,  g_h);
    cudaGetSymbolAddress((void**)&qp,  g_q);
    cudaGetSymbolAddress((void**)&kp,  g_k);
    cudaGetSymbolAddress((void**)&vp,  g_v);
    cudaGetSymbolAddress((void**)&pp,  g_p);
    cudaGetSymbolAddress((void**)&aop, g_ao);

    cudaFuncSetAttribute(attn_kernel, cudaFuncAttributeMaxDynamicSharedMemorySize, SMEM_BYTES);

    ln_kernel<<<MTOK, 128>>>(x, ln_w, ln_b, hp);

    gemm_kernel<<<dim3(8, 128), 256>>>(hp, MTOK, Wq, bq, nullptr, qp, 0);
    gemm_kernel<<<dim3(8, 128), 256>>>(hp, MTOK, Wk, bk, nullptr, kp, 0);
    gemm_kernel<<<dim3(8, 128), 256>>>(hp, MTOK, Wv, bv, nullptr, vp, 0);
    gemm_kernel<<<dim3(8, 32),  256>>>(pos_emb, CP, Wp, nullptr, nullptr, pp, 3);

    attn_kernel<<<CB * CH * (CS / 32), 256, SMEM_BYTES>>>(pbu, pbv, aop);

    gemm_kernel<<<dim3(8, 128), 256>>>(aop, MTOK, Wo, bo, x, out, 4);
}

// round 2
// speedup vs baseline: 1.3230x; 1.3230x over previous
#include <cuda_runtime.h>

// ConformerAttention: B=8, S=1024, D=512, H=8, hd=64, P=2047
// rel_shift identity: shifted[i,j] = raw[i, j + (S-1) - i] -> p row r = 1023 + j - i.

#define CB 8
#define CS 1024
#define CD 512
#define CH 8
#define CHD 64
#define CP 2047
#define MTOK (CB*CS)   // 8192

// -------- scratch (allocation-free: device globals) --------
__device__ float g_h [MTOK*CD];
__device__ float g_q [CB*CH*CS*CHD];
__device__ float g_k [CB*CH*CS*CHD];
__device__ float g_v [CB*CH*CS*CHD];
__device__ float g_p [CH*CP*CHD];
__device__ float g_ao[MTOK*CD];

// ============================ LayerNorm ============================
__global__ void __launch_bounds__(128) ln_kernel(const float* __restrict__ x,
    const float* __restrict__ w, const float* __restrict__ b, float* __restrict__ out)
{
    int row = blockIdx.x;
    int t = threadIdx.x;
    const float* xr = x + (size_t)row * CD;
    float4 v = *(const float4*)(xr + t * 4);
    float s = v.x + v.y + v.z + v.w;
    #pragma unroll
    for (int o = 16; o; o >>= 1) s += __shfl_xor_sync(0xffffffffu, s, o);
    __shared__ float ws1[4], ws2[4];
    if ((t & 31) == 0) ws1[t >> 5] = s;
    __syncthreads();
    float mean = (ws1[0] + ws1[1] + ws1[2] + ws1[3]) * (1.0f / 512.0f);
    float dx = v.x - mean, dy = v.y - mean, dz = v.z - mean, dw = v.w - mean;
    float q = dx*dx + dy*dy + dz*dz + dw*dw;
    #pragma unroll
    for (int o = 16; o; o >>= 1) q += __shfl_xor_sync(0xffffffffu, q, o);
    if ((t & 31) == 0) ws2[t >> 5] = q;
    __syncthreads();
    float var = (ws2[0] + ws2[1] + ws2[2] + ws2[3]) * (1.0f / 512.0f);
    float rstd = rsqrtf(var + 1e-5f);
    float4 wv = *(const float4*)(w + t * 4);
    float4 bv = *(const float4*)(b + t * 4);
    float4 o4;
    o4.x = dx * rstd * wv.x + bv.x;
    o4.y = dy * rstd * wv.y + bv.y;
    o4.z = dz * rstd * wv.z + bv.z;
    o4.w = dw * rstd * wv.w + bv.w;
    *(float4*)(out + (size_t)row * CD + t * 4) = o4;
}

// ============================ GEMM: C = A @ W^T ============================
__global__ void __launch_bounds__(256) gemm_kernel(
    const float* __restrict__ A, int M,
    const float* __restrict__ W,
    const float* __restrict__ bias,
    const float* __restrict__ resid,
    float* __restrict__ out, int mode)
{
    __shared__ float As[16][68];
    __shared__ float Ws[16][68];
    int tid = threadIdx.x;
    int m0 = blockIdx.y * 64, n0 = blockIdx.x * 64;
    int lm = tid >> 2;
    int lk = (tid & 3) * 4;
    int tx = tid & 15, ty = tid >> 4;
    float acc[4][4] = {};
    for (int k0 = 0; k0 < 512; k0 += 16) {
        float4 a4 = make_float4(0.f, 0.f, 0.f, 0.f);
        int am = m0 + lm;
        if (am < M) a4 = *(const float4*)(A + (size_t)am * 512 + k0 + lk);
        As[lk+0][lm] = a4.x; As[lk+1][lm] = a4.y; As[lk+2][lm] = a4.z; As[lk+3][lm] = a4.w;
        float4 w4 = *(const float4*)(W + (size_t)(n0 + lm) * 512 + k0 + lk);
        Ws[lk+0][lm] = w4.x; Ws[lk+1][lm] = w4.y; Ws[lk+2][lm] = w4.z; Ws[lk+3][lm] = w4.w;
        __syncthreads();
        #pragma unroll
        for (int kk = 0; kk < 16; kk++) {
            float4 av = *(const float4*)&As[kk][ty * 4];
            float4 wv = *(const float4*)&Ws[kk][tx * 4];
            acc[0][0] += av.x * wv.x; acc[0][1] += av.x * wv.y;
            acc[0][2] += av.x * wv.z; acc[0][3] += av.x * wv.w;
            acc[1][0] += av.y * wv.x; acc[1][1] += av.y * wv.y;
            acc[1][2] += av.y * wv.z; acc[1][3] += av.y * wv.w;
            acc[2][0] += av.z * wv.x; acc[2][1] += av.z * wv.y;
            acc[2][2] += av.z * wv.z; acc[2][3] += av.z * wv.w;
            acc[3][0] += av.w * wv.x; acc[3][1] += av.w * wv.y;
            acc[3][2] += av.w * wv.z; acc[3][3] += av.w * wv.w;
        }
        __syncthreads();
    }
    #pragma unroll
    for (int i = 0; i < 4; i++) {
        int m = m0 + ty * 4 + i;
        #pragma unroll
        for (int j = 0; j < 4; j++) {
            int n = n0 + tx * 4 + j;
            float val = acc[i][j];
            if (mode == 0) {
                val += bias[n];
                int bi = m >> 10, sr = m & 1023, hh = n >> 6, dd = n & 63;
                out[((size_t)(bi * CH + hh) << 16) + ((size_t)sr << 6) + dd] = val;
            } else if (mode == 3) {
                if (m < M) {
                    int hh = n >> 6, dd = n & 63;
                    out[((size_t)hh * CP + m) * 64 + dd] = val;
                }
            } else {
                size_t idx = (size_t)m * 512 + n;
                out[idx] = val + bias[n] + resid[idx];
            }
        }
    }
}

// ============================ Fused attention (register-tiled GEMMs) ============================
// One block per (b, h, 32-query tile). 2048 blocks, 256 threads.
// smem: sc[32][1024] scores, qut/qvt[64][36] (q+bias transposed), kbuf 17408 floats
//       (reused: kts/pts [64][264] transposed K / p-band chunks; vst [256][68]; AV partials)
constexpr int SC_F   = 32 * 1024;     // 32768
constexpr int QT_F   = 64 * 36;       // 2304
constexpr int KBUF_F = 17408;         // max(64*264=16896, 256*68=17408, 8*2048=16384)
constexpr int ASM_F  = SC_F + 2 * QT_F + KBUF_F;   // 54784 floats
constexpr int ASM_B  = ASM_F * 4;                  // 219136 bytes

__global__ void __launch_bounds__(256) attn_kernel(const float* __restrict__ bu,
    const float* __restrict__ bvp, float* __restrict__ ao)
{
    extern __shared__ float sm[];
    float* sc   = sm;                 // [32][1024]
    float* qut  = sm + SC_F;          // [64][36]  (q + bias_u)^T
    float* qvt  = qut + QT_F;         // [64][36]  (q + bias_v)^T
    float* kbuf = qvt + QT_F;         // shared staging buffer

    const int tid = threadIdx.x;
    const int w = tid >> 5, l = tid & 31;
    const int qt = blockIdx.x & 31;
    const int bh = blockIdx.x >> 5;
    const int h  = bh & 7, b = bh >> 3;
    const int i0 = qt * 32;
    const float* qbase = g_q + (size_t)bh * (CS * CHD);
    const float* kbase = g_k + (size_t)bh * (CS * CHD);
    const float* vbase = g_v + (size_t)bh * (CS * CHD);
    const float* pbase = g_p + (size_t)h  * (CP * CHD);

    // ---- Phase A: load q tile transposed, with both bias variants ----
    {
        int ii = tid & 31, dgb = tid >> 5;      // dgb 0..7
        #pragma unroll
        for (int it = 0; it < 2; it++) {
            int d4 = dgb + it * 8;              // 0..15
            float4 qv = *(const float4*)(qbase + (size_t)(i0 + ii) * 64 + d4 * 4);
            float uq[4] = {qv.x, qv.y, qv.z, qv.w};
            #pragma unroll
            for (int t = 0; t < 4; t++) {
                int d = d4 * 4 + t;
                qut[d * 36 + ii] = uq[t] + bu [h * 64 + d];
                qvt[d * 36 + ii] = uq[t] + bvp[h * 64 + d];
            }
        }
    }

    const int r8 = (l >> 3) * 8;            // acc row base (4 groups of 8 rows)
    const int cw = w * 32 + (l & 7) * 4;    // acc col base within 256-wide chunk

    // ---- Phase B1: pos scores, sheared scatter (writes every sc element once) ----
    // T[ii][r] = qv_ii . p_r for r-band [992-i0, 2046-i0]; sc[ii][j] with j = r-1023+i0+ii
    const int rlo = 992 - i0;
    for (int ch = 0; ch < 5; ch++) {
        int rbase = rlo + ch * 256;
        __syncthreads();
        {
            int r = rbase + tid;
            const float* pr = pbase + (size_t)r * 64;
            bool ok = (r < 2047);
            #pragma unroll
            for (int dg = 0; dg < 16; dg++) {
                float4 pv = ok ? *(const float4*)(pr + dg * 4) : make_float4(0.f,0.f,0.f,0.f);
                kbuf[(dg*4+0)*264 + tid] = pv.x;
                kbuf[(dg*4+1)*264 + tid] = pv.y;
                kbuf[(dg*4+2)*264 + tid] = pv.z;
                kbuf[(dg*4+3)*264 + tid] = pv.w;
            }
        }
        __syncthreads();
        float acc[8][4] = {};
        #pragma unroll 4
        for (int k = 0; k < 64; k++) {
            float4 a0 = *(const float4*)&qvt[k * 36 + r8];
            float4 a1 = *(const float4*)&qvt[k * 36 + r8 + 4];
            float4 bb = *(const float4*)&kbuf[k * 264 + cw];
            float av[8] = {a0.x,a0.y,a0.z,a0.w,a1.x,a1.y,a1.z,a1.w};
            #pragma unroll
            for (int t = 0; t < 8; t++) {
                acc[t][0] += av[t] * bb.x;
                acc[t][1] += av[t] * bb.y;
                acc[t][2] += av[t] * bb.z;
                acc[t][3] += av[t] * bb.w;
            }
        }
        int jb = rbase + cw + i0 - 1023;
        #pragma unroll
        for (int t = 0; t < 8; t++) {
            int ii = r8 + t;
            #pragma unroll
            for (int u = 0; u < 4; u++) {
                int j = jb + u + ii;
                if (j >= 0 && j < 1024) sc[ii * 1024 + j] = acc[t][u];
            }
        }
    }

    // ---- Phase B2: content scores, read-modify-write into sc ----
    for (int pass = 0; pass < 4; pass++) {
        int j0 = pass * 256;
        __syncthreads();
        {
            const float* kr = kbase + (size_t)(j0 + tid) * 64;
            #pragma unroll
            for (int dg = 0; dg < 16; dg++) {
                float4 kv = *(const float4*)(kr + dg * 4);
                kbuf[(dg*4+0)*264 + tid] = kv.x;
                kbuf[(dg*4+1)*264 + tid] = kv.y;
                kbuf[(dg*4+2)*264 + tid] = kv.z;
                kbuf[(dg*4+3)*264 + tid] = kv.w;
            }
        }
        __syncthreads();
        float acc[8][4] = {};
        #pragma unroll 4
        for (int k = 0; k < 64; k++) {
            float4 a0 = *(const float4*)&qut[k * 36 + r8];
            float4 a1 = *(const float4*)&qut[k * 36 + r8 + 4];
            float4 bb = *(const float4*)&kbuf[k * 264 + cw];
            float av[8] = {a0.x,a0.y,a0.z,a0.w,a1.x,a1.y,a1.z,a1.w};
            #pragma unroll
            for (int t = 0; t < 8; t++) {
                acc[t][0] += av[t] * bb.x;
                acc[t][1] += av[t] * bb.y;
                acc[t][2] += av[t] * bb.z;
                acc[t][3] += av[t] * bb.w;
            }
        }
        #pragma unroll
        for (int t = 0; t < 8; t++) {
            float* sp = sc + (r8 + t) * 1024 + j0 + cw;
            #pragma unroll
            for (int u = 0; u < 4; u++) sp[u] += acc[t][u];
        }
    }

    // ---- Phase C: softmax (scale 1/8 applied inside exp) ----
    __syncthreads();
    #pragma unroll
    for (int rr = 0; rr < 4; rr++) {
        int row = w * 4 + rr;
        float* rp = sc + row * 1024;
        float4 vv[8];
        float mx = -1e30f;
        #pragma unroll
        for (int g = 0; g < 8; g++) {
            vv[g] = *(const float4*)&rp[g * 128 + l * 4];
            mx = fmaxf(mx, fmaxf(fmaxf(vv[g].x, vv[g].y), fmaxf(vv[g].z, vv[g].w)));
        }
        #pragma unroll
        for (int o = 16; o; o >>= 1) mx = fmaxf(mx, __shfl_xor_sync(0xffffffffu, mx, o));
        float sum = 0.f;
        #pragma unroll
        for (int g = 0; g < 8; g++) {
            vv[g].x = __expf((vv[g].x - mx) * 0.125f);
            vv[g].y = __expf((vv[g].y - mx) * 0.125f);
            vv[g].z = __expf((vv[g].z - mx) * 0.125f);
            vv[g].w = __expf((vv[g].w - mx) * 0.125f);
            sum += vv[g].x + vv[g].y + vv[g].z + vv[g].w;
        }
        #pragma unroll
        for (int o = 16; o; o >>= 1) sum += __shfl_xor_sync(0xffffffffu, sum, o);
        float inv = 1.0f / sum;
        #pragma unroll
        for (int g = 0; g < 8; g++) {
            vv[g].x *= inv; vv[g].y *= inv; vv[g].z *= inv; vv[g].w *= inv;
            *(float4*)&rp[g * 128 + l * 4] = vv[g];
        }
    }

    // ---- Phase D: O = attn @ V, 8-way k-split, 8x8 micro ----
    const int c8 = (l & 7) * 8;
    float oacc[8][8] = {};
    for (int sc4 = 0; sc4 < 4; sc4++) {
        int k0 = sc4 * 256;
        __syncthreads();
        {
            int dg = tid & 15, kr0 = tid >> 4;
            #pragma unroll
            for (int it = 0; it < 16; it++) {
                int k = kr0 + it * 16;
                float4 vv4 = *(const float4*)(vbase + (size_t)(k0 + k) * 64 + dg * 4);
                *(float4*)&kbuf[k * 68 + dg * 4] = vv4;
            }
        }
        __syncthreads();
        int kb = w * 32;
        #pragma unroll 2
        for (int kk = 0; kk < 32; kk += 4) {
            int kg = k0 + kb + kk;
            float4 a[8];
            #pragma unroll
            for (int t = 0; t < 8; t++) a[t] = *(const float4*)&sc[(r8 + t) * 1024 + kg];
            #pragma unroll
            for (int q = 0; q < 4; q++) {
                float4 b0 = *(const float4*)&kbuf[(kb + kk + q) * 68 + c8];
                float4 b1 = *(const float4*)&kbuf[(kb + kk + q) * 68 + c8 + 4];
                #pragma unroll
                for (int t = 0; t < 8; t++) {
                    float av = (q == 0) ? a[t].x : (q == 1) ? a[t].y : (q == 2) ? a[t].z : a[t].w;
                    oacc[t][0] += av * b0.x; oacc[t][1] += av * b0.y;
                    oacc[t][2] += av * b0.z; oacc[t][3] += av * b0.w;
                    oacc[t][4] += av * b1.x; oacc[t][5] += av * b1.y;
                    oacc[t][6] += av * b1.z; oacc[t][7] += av * b1.w;
                }
            }
        }
    }
    // write per-warp partials, then reduce across warps
    __syncthreads();
    #pragma unroll
    for (int t = 0; t < 8; t++) {
        *(float4*)&kbuf[w * 2048 + (r8 + t) * 64 + c8]     = make_float4(oacc[t][0], oacc[t][1], oacc[t][2], oacc[t][3]);
        *(float4*)&kbuf[w * 2048 + (r8 + t) * 64 + c8 + 4] = make_float4(oacc[t][4], oacc[t][5], oacc[t][6], oacc[t][7]);
    }
    __syncthreads();
    #pragma unroll
    for (int rep = 0; rep < 2; rep++) {
        int e = tid + rep * 256;            // float4 index 0..511
        float4 s = make_float4(0.f, 0.f, 0.f, 0.f);
        #pragma unroll
        for (int ww = 0; ww < 8; ww++) {
            float4 p4 = *(const float4*)&kbuf[ww * 2048 + e * 4];
            s.x += p4.x; s.y += p4.y; s.z += p4.z; s.w += p4.w;
        }
        int ii = e >> 4;
        int d  = (e & 15) * 4;
        *(float4*)&ao[(size_t)(b * 1024 + i0 + ii) * 512 + h * 64 + d] = s;
    }
}

// ============================ launch ============================
extern "C" void kernel_launch(void* const* d_in, const int* in_sizes, int n_in,
                              void* d_out, int out_size)
{
    const float* x       = (const float*)d_in[0];
    const float* pos_emb = (const float*)d_in[1];
    const float* ln_w    = (const float*)d_in[2];
    const float* ln_b    = (const float*)d_in[3];
    const float* Wq      = (const float*)d_in[4];
    const float* bq      = (const float*)d_in[5];
    const float* Wk      = (const float*)d_in[6];
    const float* bk      = (const float*)d_in[7];
    const float* Wv      = (const float*)d_in[8];
    const float* bv      = (const float*)d_in[9];
    const float* Wo      = (const float*)d_in[10];
    const float* bo      = (const float*)d_in[11];
    const float* Wp      = (const float*)d_in[12];
    const float* pbu     = (const float*)d_in[13];
    const float* pbv     = (const float*)d_in[14];
    float* out = (float*)d_out;

    float *hp, *qp, *kp, *vp, *pp, *aop;
    cudaGetSymbolAddress((void**)&hp,  g_h);
    cudaGetSymbolAddress((void**)&qp,  g_q);
    cudaGetSymbolAddress((void**)&kp,  g_k);
    cudaGetSymbolAddress((void**)&vp,  g_v);
    cudaGetSymbolAddress((void**)&pp,  g_p);
    cudaGetSymbolAddress((void**)&aop, g_ao);

    cudaFuncSetAttribute(attn_kernel, cudaFuncAttributeMaxDynamicSharedMemorySize, ASM_B);

    ln_kernel<<<MTOK, 128>>>(x, ln_w, ln_b, hp);

    gemm_kernel<<<dim3(8, 128), 256>>>(hp, MTOK, Wq, bq, nullptr, qp, 0);
    gemm_kernel<<<dim3(8, 128), 256>>>(hp, MTOK, Wk, bk, nullptr, kp, 0);
    gemm_kernel<<<dim3(8, 128), 256>>>(hp, MTOK, Wv, bv, nullptr, vp, 0);
    gemm_kernel<<<dim3(8, 32),  256>>>(pos_emb, CP, Wp, nullptr, nullptr, pp, 3);

    attn_kernel<<<CB * CH * (CS / 32), 256, ASM_B>>>(pbu, pbv, aop);

    gemm_kernel<<<dim3(8, 128), 256>>>(aop, MTOK, Wo, bo, x, out, 4);
}